// round 12
// baseline (speedup 1.0000x reference)
#include <cuda_runtime.h>
#include <math.h>

#define SEQV  5
#define ALPHA 0.2f

// Precomputed transposed column-softmax of w_raw, padded rows of 66:
// g_Wt[d*66 + c] = softmax(w_raw*500, axis=0)[c][d]
__device__ float g_Wt[64 * 66];

// ---- 8-lane (octet) reductions: xor 1,2,4 stay inside the octet ----
__device__ __forceinline__ float omax8(float v) {
    v = fmaxf(v, __shfl_xor_sync(0xffffffffu, v, 1));
    v = fmaxf(v, __shfl_xor_sync(0xffffffffu, v, 2));
    v = fmaxf(v, __shfl_xor_sync(0xffffffffu, v, 4));
    return v;
}
__device__ __forceinline__ float osum8(float v) {
    v += __shfl_xor_sync(0xffffffffu, v, 1);
    v += __shfl_xor_sync(0xffffffffu, v, 2);
    v += __shfl_xor_sync(0xffffffffu, v, 4);
    return v;
}

// ---------------------------------------------------------------------------
// Prep kernel: block d computes softmax column d of w_raw*500 (runs once).
// ---------------------------------------------------------------------------
__global__ void prep_w_kernel(const float* __restrict__ w_raw) {
    const int d = blockIdx.x;      // column
    const int c = threadIdx.x;     // row
    __shared__ float red[4];

    float val = w_raw[c * 64 + d] * 500.0f;          // 100 * GAMMA2
    float m = val;
#pragma unroll
    for (int off = 16; off; off >>= 1)
        m = fmaxf(m, __shfl_xor_sync(0xffffffffu, m, off));
    if ((c & 31) == 0) red[c >> 5] = m;
    __syncthreads();
    m = fmaxf(red[0], red[1]);

    float e = __expf(val - m);
    float Z = e;
#pragma unroll
    for (int off = 16; off; off >>= 1)
        Z += __shfl_xor_sync(0xffffffffu, Z, off);
    if ((c & 31) == 0) red[2 + (c >> 5)] = Z;
    __syncthreads();
    Z = red[2] + red[3];

    g_Wt[d * 66 + c] = __fdividef(e, Z);
}

// ---------------------------------------------------------------------------
// Main kernel: 128 threads = 4 warps = 16 batch elements per block (4 per
// warp, one per 8-lane octet). W copied from the precomputed global.
// Sequence scores computed in a first pass with 5 INDEPENDENT chains (no
// online-softmax serialization); softmax over 5 is pure scalar math; the
// weighted item-sum pass re-gathers the rows from L1 (guaranteed hits).
// ---------------------------------------------------------------------------
__global__ __launch_bounds__(128, 7) void rumc_kernel(
    const int*   __restrict__ u,
    const int*   __restrict__ X,
    const int*   __restrict__ y,
    const float* __restrict__ item_emb,
    const float* __restrict__ user_emb,
    const float* __restrict__ ae_raw,
    float*       __restrict__ out,
    int B)
{
    __shared__ float sW[64 * 66];      // 16.9KB
    __shared__ float sAV[16 * 68];     // ae[y] per b, overwritten in-place by v

    const int tid  = threadIdx.x;
    const int warp = tid >> 5;
    const int lane = tid & 31;
    const int o    = lane >> 3;
    const int k8   = lane & 7;

    const int bloc = warp * 4 + o;     // 0..15 within block
    int b = blockIdx.x * 16 + bloc;
    const bool valid = (b < B);
    if (!valid) b = B - 1;

    // ---- issue index loads + ae[y] gather FIRST (overlap with W copy) ----
    const int yi = y[b];
    const int ui = u[b];
    int xs[SEQV];
#pragma unroll
    for (int s = 0; s < SEQV; s++) xs[s] = X[b * SEQV + s];

    const float* ayp = ae_raw + (size_t)yi * 64;
    float4 A0 = *(const float4*)(ayp + 4 * k8);
    float4 A1 = *(const float4*)(ayp + 32 + 4 * k8);

    // ================= copy precomputed W into smem ==========================
    {
        // 64*66 floats = 1056 float4: 8 strides of 128 threads + 32 remainder
        const float4* src = (const float4*)g_Wt;
        float4*       dst = (float4*)sW;
#pragma unroll
        for (int i = 0; i < 8; i++)
            dst[tid + 128 * i] = src[tid + 128 * i];
        if (tid < 32)
            dst[tid + 1024] = src[tid + 1024];
    }

    // ================= ae[y] softmax -> smem =================================
    {
        float a0 = A0.x * 50.0f, a1 = A0.y * 50.0f, a2 = A0.z * 50.0f, a3 = A0.w * 50.0f;
        float a4 = A1.x * 50.0f, a5 = A1.y * 50.0f, a6 = A1.z * 50.0f, a7 = A1.w * 50.0f;
        float m = fmaxf(fmaxf(fmaxf(a0, a1), fmaxf(a2, a3)),
                        fmaxf(fmaxf(a4, a5), fmaxf(a6, a7)));
        m = omax8(m);
        a0 = __expf(a0 - m); a1 = __expf(a1 - m); a2 = __expf(a2 - m); a3 = __expf(a3 - m);
        a4 = __expf(a4 - m); a5 = __expf(a5 - m); a6 = __expf(a6 - m); a7 = __expf(a7 - m);
        float Z = osum8(((a0 + a1) + (a2 + a3)) + ((a4 + a5) + (a6 + a7)));
        float inv = __fdividef(1.0f, Z);
        *(float4*)(sAV + bloc * 68 + 4 * k8) =
            make_float4(a0 * inv, a1 * inv, a2 * inv, a3 * inv);
        *(float4*)(sAV + bloc * 68 + 32 + 4 * k8) =
            make_float4(a4 * inv, a5 * inv, a6 * inv, a7 * inv);
    }

    // ---- prefetch y-item row, step-0 ae row, step-0 item row ----
    float4 Y0 = make_float4(0.f, 0.f, 0.f, 0.f);
    float4 Y1 = make_float4(0.f, 0.f, 0.f, 0.f);
    if (yi != 0) {
        const float* yp = item_emb + (size_t)yi * 64;
        Y0 = *(const float4*)(yp + 4 * k8);
        Y1 = *(const float4*)(yp + 32 + 4 * k8);
    }
    // ae-row double buffer (depth-2 prefetch), slot s&1
    float4 Fb0[2], Fb1[2];
    {
        const float* ax0 = ae_raw + (size_t)xs[0] * 64;
        Fb0[0] = *(const float4*)(ax0 + 4 * k8);
        Fb1[0] = *(const float4*)(ax0 + 32 + 4 * k8);
    }
    // item-row single buffer (depth-1 prefetch)
    float4 Xc0 = make_float4(0.f, 0.f, 0.f, 0.f);
    float4 Xc1 = make_float4(0.f, 0.f, 0.f, 0.f);
    if (xs[0] != 0) {
        const float* xp = item_emb + (size_t)xs[0] * 64;
        Xc0 = *(const float4*)(xp + 4 * k8);
        Xc1 = *(const float4*)(xp + 32 + 4 * k8);
    }

    __syncthreads();   // W copy complete

    // ================= batched mat-vec: 4 b per warp ==========================
    {
        float acc0x = 0.f, acc0y = 0.f, acc1x = 0.f, acc1y = 0.f;
        float acc2x = 0.f, acc2y = 0.f, acc3x = 0.f, acc3y = 0.f;
        const int bB = warp * 4;
        const float* aey0 = sAV + (bB + 0) * 68;
        const float* aey1 = sAV + (bB + 1) * 68;
        const float* aey2 = sAV + (bB + 2) * 68;
        const float* aey3 = sAV + (bB + 3) * 68;
#pragma unroll
        for (int d4 = 0; d4 < 16; d4++) {
            float2 w0 = *(const float2*)(sW + (4 * d4 + 0) * 66 + 2 * lane);
            float2 w1 = *(const float2*)(sW + (4 * d4 + 1) * 66 + 2 * lane);
            float2 w2 = *(const float2*)(sW + (4 * d4 + 2) * 66 + 2 * lane);
            float2 w3 = *(const float2*)(sW + (4 * d4 + 3) * 66 + 2 * lane);

            float4 a;
            a = *(const float4*)(aey0 + 4 * d4);
            acc0x = fmaf(w0.x, a.x, fmaf(w1.x, a.y, fmaf(w2.x, a.z, fmaf(w3.x, a.w, acc0x))));
            acc0y = fmaf(w0.y, a.x, fmaf(w1.y, a.y, fmaf(w2.y, a.z, fmaf(w3.y, a.w, acc0y))));
            a = *(const float4*)(aey1 + 4 * d4);
            acc1x = fmaf(w0.x, a.x, fmaf(w1.x, a.y, fmaf(w2.x, a.z, fmaf(w3.x, a.w, acc1x))));
            acc1y = fmaf(w0.y, a.x, fmaf(w1.y, a.y, fmaf(w2.y, a.z, fmaf(w3.y, a.w, acc1y))));
            a = *(const float4*)(aey2 + 4 * d4);
            acc2x = fmaf(w0.x, a.x, fmaf(w1.x, a.y, fmaf(w2.x, a.z, fmaf(w3.x, a.w, acc2x))));
            acc2y = fmaf(w0.y, a.x, fmaf(w1.y, a.y, fmaf(w2.y, a.z, fmaf(w3.y, a.w, acc2y))));
            a = *(const float4*)(aey3 + 4 * d4);
            acc3x = fmaf(w0.x, a.x, fmaf(w1.x, a.y, fmaf(w2.x, a.z, fmaf(w3.x, a.w, acc3x))));
            acc3y = fmaf(w0.y, a.x, fmaf(w1.y, a.y, fmaf(w2.y, a.z, fmaf(w3.y, a.w, acc3y))));
        }
        __syncwarp();   // all aey reads done before in-place v stores
        *(float2*)(sAV + (bB + 0) * 68 + 2 * lane) = make_float2(acc0x, acc0y);
        *(float2*)(sAV + (bB + 1) * 68 + 2 * lane) = make_float2(acc1x, acc1y);
        *(float2*)(sAV + (bB + 2) * 68 + 2 * lane) = make_float2(acc2x, acc2y);
        *(float2*)(sAV + (bB + 3) * 68 + 2 * lane) = make_float2(acc3x, acc3y);
    }
    __syncwarp();

    // ================= pass A: scores (5 independent chains) ==================
    float4 V0 = *(const float4*)(sAV + bloc * 68 + 4 * k8);
    float4 V1 = *(const float4*)(sAV + bloc * 68 + 32 + 4 * k8);

    // prime depth-2: step-1 ae row
    {
        const float* ax1 = ae_raw + (size_t)xs[1] * 64;
        Fb0[1] = *(const float4*)(ax1 + 4 * k8);
        Fb1[1] = *(const float4*)(ax1 + 32 + 4 * k8);
    }

    float sc[SEQV];
#pragma unroll
    for (int s = 0; s < SEQV; s++) {
        float4 F0 = Fb0[s & 1], F1 = Fb1[s & 1];
        float4 X0 = Xc0, X1 = Xc1;

        if (s + 2 < SEQV) {            // depth-2 ae refill
            const float* axn = ae_raw + (size_t)xs[s + 2] * 64;
            Fb0[s & 1] = *(const float4*)(axn + 4 * k8);
            Fb1[s & 1] = *(const float4*)(axn + 32 + 4 * k8);
        }
        if (s + 1 < SEQV) {            // depth-1 item prefetch
            const int xn = xs[s + 1];
            if (xn != 0) {
                const float* xpn = item_emb + (size_t)xn * 64;
                Xc0 = *(const float4*)(xpn + 4 * k8);
                Xc1 = *(const float4*)(xpn + 32 + 4 * k8);
            } else {
                Xc0 = make_float4(0.f, 0.f, 0.f, 0.f);
                Xc1 = make_float4(0.f, 0.f, 0.f, 0.f);
            }
        }

        float f0 = F0.x * 50.0f, f1 = F0.y * 50.0f, f2 = F0.z * 50.0f, f3 = F0.w * 50.0f;
        float f4 = F1.x * 50.0f, f5 = F1.y * 50.0f, f6 = F1.z * 50.0f, f7 = F1.w * 50.0f;
        float mm = fmaxf(fmaxf(fmaxf(f0, f1), fmaxf(f2, f3)),
                         fmaxf(fmaxf(f4, f5), fmaxf(f6, f7)));
        mm = omax8(mm);
        f0 = __expf(f0 - mm); f1 = __expf(f1 - mm);
        f2 = __expf(f2 - mm); f3 = __expf(f3 - mm);
        f4 = __expf(f4 - mm); f5 = __expf(f5 - mm);
        f6 = __expf(f6 - mm); f7 = __expf(f7 - mm);
        float num = fmaf(f0, V0.x, fmaf(f1, V0.y, fmaf(f2, V0.z, f3 * V0.w)));
        num = fmaf(f4, V1.x, fmaf(f5, V1.y, fmaf(f6, V1.z, fmaf(f7, V1.w, num))));
        float den = ((f0 + f1) + (f2 + f3)) + ((f4 + f5) + (f6 + f7));
        float dot = fmaf(X0.x, Y0.x, fmaf(X0.y, Y0.y, fmaf(X0.z, Y0.z, X0.w * Y0.w)));
        dot = fmaf(X1.x, Y1.x, fmaf(X1.y, Y1.y, fmaf(X1.z, Y1.z, fmaf(X1.w, Y1.w, dot))));
        num = osum8(num);
        den = osum8(den);
        dot = osum8(dot);

        const float tf = 0.6f + 0.1f * (float)s;     // time factor, BETA=1
        sc[s] = dot * __expf(__fdividef(num, den)) * tf;
    }

    // ================= softmax over 5 (scalar, no shuffles) ===================
    float msc = fmaxf(fmaxf(fmaxf(sc[0], sc[1]), fmaxf(sc[2], sc[3])), sc[4]);
    float Zs = 0.0f;
#pragma unroll
    for (int s = 0; s < SEQV; s++) {
        sc[s] = __expf(sc[s] - msc);
        Zs += sc[s];
    }

    // user row: issue now (covered by pass B)
    const float* up = user_emb + (size_t)ui * 64;
    float4 U0 = *(const float4*)(up + 4 * k8);
    float4 U1 = *(const float4*)(up + 32 + 4 * k8);

    // ================= pass B: p = sum_s z_s * X_s (L1-hit reloads) ===========
    float4 P0 = make_float4(0.f, 0.f, 0.f, 0.f);
    float4 P1 = make_float4(0.f, 0.f, 0.f, 0.f);
#pragma unroll
    for (int s = 0; s < SEQV; s++) {
        const int xi = xs[s];
        if (xi != 0) {
            const float* xp = item_emb + (size_t)xi * 64;
            float4 X0 = *(const float4*)(xp + 4 * k8);       // L1 hit
            float4 X1 = *(const float4*)(xp + 32 + 4 * k8);  // L1 hit
            const float z = sc[s];
            P0.x = fmaf(z, X0.x, P0.x); P0.y = fmaf(z, X0.y, P0.y);
            P0.z = fmaf(z, X0.z, P0.z); P0.w = fmaf(z, X0.w, P0.w);
            P1.x = fmaf(z, X1.x, P1.x); P1.y = fmaf(z, X1.y, P1.y);
            P1.z = fmaf(z, X1.z, P1.z); P1.w = fmaf(z, X1.w, P1.w);
        }
    }

    const float scale = __fdividef(ALPHA, Zs);
    float d;
    d =          fmaf(P0.x, scale, U0.x) * Y0.x;
    d = fmaf(fmaf(P0.y, scale, U0.y), Y0.y, d);
    d = fmaf(fmaf(P0.z, scale, U0.z), Y0.z, d);
    d = fmaf(fmaf(P0.w, scale, U0.w), Y0.w, d);
    d = fmaf(fmaf(P1.x, scale, U1.x), Y1.x, d);
    d = fmaf(fmaf(P1.y, scale, U1.y), Y1.y, d);
    d = fmaf(fmaf(P1.z, scale, U1.z), Y1.z, d);
    d = fmaf(fmaf(P1.w, scale, U1.w), Y1.w, d);
    d = osum8(d);

    if (valid && k8 == 0)
        out[b] = __fdividef(1.0f, 1.0f + __expf(-d));
}

// ---------------------------------------------------------------------------
// Launcher — inputs (metadata order): u[int B], X[int B*5], y[int B],
//   item_emb[f32 (I+1)*64], user_emb[f32 U*64], ae_raw[f32 (I+1)*64],
//   w_raw[f32 64*64].  Output: f32 [B].
// ---------------------------------------------------------------------------
extern "C" void kernel_launch(void* const* d_in, const int* in_sizes, int n_in,
                              void* d_out, int out_size) {
    const int*   u        = (const int*)  d_in[0];
    const int*   X        = (const int*)  d_in[1];
    const int*   y        = (const int*)  d_in[2];
    const float* item_emb = (const float*)d_in[3];
    const float* user_emb = (const float*)d_in[4];
    const float* ae_raw   = (const float*)d_in[5];
    const float* w_raw    = (const float*)d_in[6];
    float* out = (float*)d_out;

    const int B = in_sizes[0];

    prep_w_kernel<<<64, 64>>>(w_raw);

    const int blocks = (B + 15) / 16;   // 16 batch elems per 128-thread block
    rumc_kernel<<<blocks, 128>>>(u, X, y, item_emb, user_emb, ae_raw, out, B);
}